// round 9
// baseline (speedup 1.0000x reference)
#include <cuda_runtime.h>
#include <math.h>

// Problem constants (fixed by the dataset)
#define T_TOK 8192      // B*N tokens
#define EMB   1024
#define HID   1536
#define NE    8
#define TOPK  2

// GEMM tiling
#define BM 128
#define BN 128
#define BK 8

// ---------------- device scratch (static: no allocations allowed) ----------
__device__ int   g_cnt[NE];                 // tokens per expert
__device__ int   g_off[NE];                 // exclusive scan of g_cnt
__device__ int   g_tok[NE * T_TOK];         // gathered token ids per expert
__device__ float g_h[(size_t)T_TOK * TOPK * HID];  // hidden activations (16384 x 1536)

// ---------------- kernel 1: zero output + reset counters -------------------
__global__ void zero_kernel(float4* __restrict__ out, int n4) {
    if (blockIdx.x == 0 && threadIdx.x < NE) g_cnt[threadIdx.x] = 0;
    int i = blockIdx.x * blockDim.x + threadIdx.x;
    float4 z = make_float4(0.f, 0.f, 0.f, 0.f);
    for (; i < n4; i += gridDim.x * blockDim.x) out[i] = z;
}

// ---------------- kernel 2: router (warp per token, top-2) -----------------
__global__ void router_kernel(const float* __restrict__ x,
                              const float* __restrict__ Wr,
                              const float* __restrict__ br) {
    int gw   = (blockIdx.x * blockDim.x + threadIdx.x) >> 5;
    int lane = threadIdx.x & 31;
    if (gw >= T_TOK) return;
    const float* xr = x + (size_t)gw * EMB;
    float acc[NE];
#pragma unroll
    for (int e = 0; e < NE; e++) acc[e] = 0.f;
    for (int j = lane; j < EMB; j += 32) {
        float xv = xr[j];
        const float4* w = (const float4*)(Wr + (size_t)j * NE);
        float4 w0 = w[0], w1 = w[1];
        acc[0] += xv * w0.x; acc[1] += xv * w0.y;
        acc[2] += xv * w0.z; acc[3] += xv * w0.w;
        acc[4] += xv * w1.x; acc[5] += xv * w1.y;
        acc[6] += xv * w1.z; acc[7] += xv * w1.w;
    }
#pragma unroll
    for (int e = 0; e < NE; e++) {
#pragma unroll
        for (int off = 16; off > 0; off >>= 1)
            acc[e] += __shfl_xor_sync(0xffffffffu, acc[e], off);
    }
    if (lane == 0) {
        float l[NE];
#pragma unroll
        for (int e = 0; e < NE; e++) l[e] = acc[e] + br[e];
        // top-1: strict > keeps lowest index on ties (matches jax top_k)
        int i1 = 0; float v1 = l[0];
#pragma unroll
        for (int e = 1; e < NE; e++) if (l[e] > v1) { v1 = l[e]; i1 = e; }
        int i2 = -1; float v2 = -3.4e38f;
#pragma unroll
        for (int e = 0; e < NE; e++)
            if (e != i1 && l[e] > v2) { v2 = l[e]; i2 = e; }
        int p1 = atomicAdd(&g_cnt[i1], 1); g_tok[i1 * T_TOK + p1] = gw;
        int p2 = atomicAdd(&g_cnt[i2], 1); g_tok[i2 * T_TOK + p2] = gw;
    }
}

// ---------------- kernel 3: exclusive scan of counts (tiny) ----------------
__global__ void offs_kernel() {
    if (blockIdx.x == 0 && threadIdx.x == 0) {
        int s = 0;
        for (int e = 0; e < NE; e++) { g_off[e] = s; s += g_cnt[e]; }
    }
}

__device__ __forceinline__ float gelu_exact(float v) {
    return 0.5f * v * (1.0f + erff(v * 0.70710678118654752440f));
}

// ---------------- kernel 4: grouped GEMM1  h = gelu(X_sel @ W1[e] + b1) ----
// grid: (T_TOK/BM, HID/BN, NE); block 256; 8x8 register micro-tile.
__global__ __launch_bounds__(256, 2) void gemm1_kernel(
        const float* __restrict__ x, const float* __restrict__ W1,
        const float* __restrict__ b1) {
    const int e  = blockIdx.z;
    const int M  = g_cnt[e];
    const int m0 = blockIdx.x * BM;
    if (m0 >= M) return;
    const int n0 = blockIdx.y * BN;

    __shared__ float As[BK][BM];
    __shared__ float Bs[BK][BN];

    const int tid = threadIdx.x;
    const int tx = tid & 15, ty = tid >> 4;

    // A (gathered x rows): 2 threads per row, float4 each
    int ar = tid >> 1;
    int ac = (tid & 1) * 4;
    int mi = m0 + ar; if (mi > M - 1) mi = M - 1;       // clamp; masked at store
    const float* aptr = x + (size_t)g_tok[e * T_TOK + mi] * EMB + ac;

    // B (W1[e], [E][H] row-major): 32 threads per k-row, float4 each
    int bk = tid >> 5;
    int bn = (tid & 31) * 4;
    const float* bptr = W1 + (size_t)e * EMB * HID + (size_t)bk * HID + n0 + bn;

    float acc[8][8];
#pragma unroll
    for (int i = 0; i < 8; i++)
#pragma unroll
        for (int j = 0; j < 8; j++) acc[i][j] = 0.f;

    for (int k0 = 0; k0 < EMB; k0 += BK) {
        float4 av = *(const float4*)(aptr + k0);
        float4 bv = *(const float4*)(bptr + (size_t)k0 * HID);
        __syncthreads();
        As[ac + 0][ar] = av.x; As[ac + 1][ar] = av.y;
        As[ac + 2][ar] = av.z; As[ac + 3][ar] = av.w;
        *(float4*)&Bs[bk][bn] = bv;
        __syncthreads();
#pragma unroll
        for (int kk = 0; kk < BK; kk++) {
            float4 a0 = *(const float4*)&As[kk][ty * 8];
            float4 a1 = *(const float4*)&As[kk][ty * 8 + 4];
            float4 b0 = *(const float4*)&Bs[kk][tx * 8];
            float4 b1f = *(const float4*)&Bs[kk][tx * 8 + 4];
            float a[8] = {a0.x, a0.y, a0.z, a0.w, a1.x, a1.y, a1.z, a1.w};
            float b[8] = {b0.x, b0.y, b0.z, b0.w, b1f.x, b1f.y, b1f.z, b1f.w};
#pragma unroll
            for (int i = 0; i < 8; i++)
#pragma unroll
                for (int j = 0; j < 8; j++) acc[i][j] += a[i] * b[j];
        }
    }

    const int base = g_off[e];
    float bb[8];
#pragma unroll
    for (int j = 0; j < 8; j++) bb[j] = b1[(size_t)e * HID + n0 + tx * 8 + j];
#pragma unroll
    for (int i = 0; i < 8; i++) {
        int m = m0 + ty * 8 + i;
        if (m < M) {
            float* dst = g_h + (size_t)(base + m) * HID + n0 + tx * 8;
            float v[8];
#pragma unroll
            for (int j = 0; j < 8; j++) v[j] = gelu_exact(acc[i][j] + bb[j]);
            *(float4*)dst       = make_float4(v[0], v[1], v[2], v[3]);
            *(float4*)(dst + 4) = make_float4(v[4], v[5], v[6], v[7]);
        }
    }
}

// ---------------- kernel 5: grouped GEMM2  out += 0.5*(h @ W2[e] + b2) -----
// grid: (T_TOK/BM, EMB/BN, NE); block 256.
__global__ __launch_bounds__(256, 2) void gemm2_kernel(
        const float* __restrict__ W2, const float* __restrict__ b2,
        float* __restrict__ out) {
    const int e  = blockIdx.z;
    const int M  = g_cnt[e];
    const int m0 = blockIdx.x * BM;
    if (m0 >= M) return;
    const int n0 = blockIdx.y * BN;
    const int base = g_off[e];

    __shared__ float As[BK][BM];
    __shared__ float Bs[BK][BN];

    const int tid = threadIdx.x;
    const int tx = tid & 15, ty = tid >> 4;

    int ar = tid >> 1;
    int ac = (tid & 1) * 4;
    int mi = m0 + ar; if (mi > M - 1) mi = M - 1;
    const float* aptr = g_h + (size_t)(base + mi) * HID + ac;

    int bk = tid >> 5;
    int bn = (tid & 31) * 4;
    const float* bptr = W2 + (size_t)e * HID * EMB + (size_t)bk * EMB + n0 + bn;

    float acc[8][8];
#pragma unroll
    for (int i = 0; i < 8; i++)
#pragma unroll
        for (int j = 0; j < 8; j++) acc[i][j] = 0.f;

    for (int k0 = 0; k0 < HID; k0 += BK) {
        float4 av = *(const float4*)(aptr + k0);
        float4 bv = *(const float4*)(bptr + (size_t)k0 * EMB);
        __syncthreads();
        As[ac + 0][ar] = av.x; As[ac + 1][ar] = av.y;
        As[ac + 2][ar] = av.z; As[ac + 3][ar] = av.w;
        *(float4*)&Bs[bk][bn] = bv;
        __syncthreads();
#pragma unroll
        for (int kk = 0; kk < BK; kk++) {
            float4 a0 = *(const float4*)&As[kk][ty * 8];
            float4 a1 = *(const float4*)&As[kk][ty * 8 + 4];
            float4 b0 = *(const float4*)&Bs[kk][tx * 8];
            float4 b1f = *(const float4*)&Bs[kk][tx * 8 + 4];
            float a[8] = {a0.x, a0.y, a0.z, a0.w, a1.x, a1.y, a1.z, a1.w};
            float b[8] = {b0.x, b0.y, b0.z, b0.w, b1f.x, b1f.y, b1f.z, b1f.w};
#pragma unroll
            for (int i = 0; i < 8; i++)
#pragma unroll
                for (int j = 0; j < 8; j++) acc[i][j] += a[i] * b[j];
        }
    }

    float bb[8];
#pragma unroll
    for (int j = 0; j < 8; j++) bb[j] = b2[(size_t)e * EMB + n0 + tx * 8 + j];
#pragma unroll
    for (int i = 0; i < 8; i++) {
        int m = m0 + ty * 8 + i;
        if (m < M) {
            int tok = g_tok[e * T_TOK + m];
            float* dst = out + (size_t)tok * EMB + n0 + tx * 8;
            // exactly 2 contributions per output element -> commutative -> deterministic
#pragma unroll
            for (int j = 0; j < 8; j++)
                atomicAdd(dst + j, 0.5f * (acc[i][j] + bb[j]));
        }
    }
}

// ---------------- launch ----------------------------------------------------
extern "C" void kernel_launch(void* const* d_in, const int* in_sizes, int n_in,
                              void* d_out, int out_size) {
    const float* x  = (const float*)d_in[0];
    const float* Wr = (const float*)d_in[1];
    const float* br = (const float*)d_in[2];
    const float* W1 = (const float*)d_in[3];
    const float* b1 = (const float*)d_in[4];
    const float* W2 = (const float*)d_in[5];
    const float* b2 = (const float*)d_in[6];
    // d_in[7] is k (fixed at 2 for this dataset)
    float* out = (float*)d_out;

    int n4 = out_size / 4;  // out is fp32, out_size % 4 == 0 (T*E)
    zero_kernel<<<(n4 + 255) / 256, 256>>>((float4*)out, n4);
    router_kernel<<<T_TOK / 8, 256>>>(x, Wr, br);
    offs_kernel<<<1, 32>>>();
    gemm1_kernel<<<dim3(T_TOK / BM, HID / BN, NE), 256>>>(x, W1, b1);
    gemm2_kernel<<<dim3(T_TOK / BM, EMB / BN, NE), 256>>>(W2, b2, out);
}

// round 10
// speedup vs baseline: 1.0017x; 1.0017x over previous
#include <cuda_runtime.h>
#include <math.h>

// Problem constants (fixed by the dataset)
#define T_TOK 8192      // B*N tokens
#define EMB   1024
#define HID   1536
#define NE    8
#define TOPK  2

// GEMM tiling
#define BM 128
#define BN 128
#define BK 8

// ---------------- device scratch (static: no allocations allowed) ----------
__device__ int   g_cnt[NE];                 // tokens per expert
__device__ int   g_off[NE];                 // exclusive scan of g_cnt
__device__ int   g_tok[NE * T_TOK];         // gathered token ids per expert
__device__ float g_h[(size_t)T_TOK * TOPK * HID];  // hidden activations (16384 x 1536)

// ---------------- kernel 1: zero output + reset counters -------------------
__global__ void zero_kernel(float4* __restrict__ out, int n4) {
    if (blockIdx.x == 0 && threadIdx.x < NE) g_cnt[threadIdx.x] = 0;
    int i = blockIdx.x * blockDim.x + threadIdx.x;
    float4 z = make_float4(0.f, 0.f, 0.f, 0.f);
    for (; i < n4; i += gridDim.x * blockDim.x) out[i] = z;
}

// ---------------- kernel 2: router (warp per token, top-2) -----------------
__global__ void router_kernel(const float* __restrict__ x,
                              const float* __restrict__ Wr,
                              const float* __restrict__ br) {
    int gw   = (blockIdx.x * blockDim.x + threadIdx.x) >> 5;
    int lane = threadIdx.x & 31;
    if (gw >= T_TOK) return;
    const float* xr = x + (size_t)gw * EMB;
    float acc[NE];
#pragma unroll
    for (int e = 0; e < NE; e++) acc[e] = 0.f;
    for (int j = lane; j < EMB; j += 32) {
        float xv = xr[j];
        const float4* w = (const float4*)(Wr + (size_t)j * NE);
        float4 w0 = w[0], w1 = w[1];
        acc[0] += xv * w0.x; acc[1] += xv * w0.y;
        acc[2] += xv * w0.z; acc[3] += xv * w0.w;
        acc[4] += xv * w1.x; acc[5] += xv * w1.y;
        acc[6] += xv * w1.z; acc[7] += xv * w1.w;
    }
#pragma unroll
    for (int e = 0; e < NE; e++) {
#pragma unroll
        for (int off = 16; off > 0; off >>= 1)
            acc[e] += __shfl_xor_sync(0xffffffffu, acc[e], off);
    }
    if (lane == 0) {
        float l[NE];
#pragma unroll
        for (int e = 0; e < NE; e++) l[e] = acc[e] + br[e];
        // top-1: strict > keeps lowest index on ties (matches jax top_k)
        int i1 = 0; float v1 = l[0];
#pragma unroll
        for (int e = 1; e < NE; e++) if (l[e] > v1) { v1 = l[e]; i1 = e; }
        int i2 = -1; float v2 = -3.4e38f;
#pragma unroll
        for (int e = 0; e < NE; e++)
            if (e != i1 && l[e] > v2) { v2 = l[e]; i2 = e; }
        int p1 = atomicAdd(&g_cnt[i1], 1); g_tok[i1 * T_TOK + p1] = gw;
        int p2 = atomicAdd(&g_cnt[i2], 1); g_tok[i2 * T_TOK + p2] = gw;
    }
}

// ---------------- kernel 3: exclusive scan of counts (tiny) ----------------
__global__ void offs_kernel() {
    if (blockIdx.x == 0 && threadIdx.x == 0) {
        int s = 0;
        for (int e = 0; e < NE; e++) { g_off[e] = s; s += g_cnt[e]; }
    }
}

__device__ __forceinline__ float gelu_exact(float v) {
    return 0.5f * v * (1.0f + erff(v * 0.70710678118654752440f));
}

// ---------------- kernel 4: grouped GEMM1  h = gelu(X_sel @ W1[e] + b1) ----
// grid: (T_TOK/BM, HID/BN, NE); block 256; 8x8 register micro-tile.
__global__ __launch_bounds__(256, 2) void gemm1_kernel(
        const float* __restrict__ x, const float* __restrict__ W1,
        const float* __restrict__ b1) {
    const int e  = blockIdx.z;
    const int M  = g_cnt[e];
    const int m0 = blockIdx.x * BM;
    if (m0 >= M) return;
    const int n0 = blockIdx.y * BN;

    __shared__ float As[BK][BM];
    __shared__ float Bs[BK][BN];

    const int tid = threadIdx.x;
    const int tx = tid & 15, ty = tid >> 4;

    // A (gathered x rows): 2 threads per row, float4 each
    int ar = tid >> 1;
    int ac = (tid & 1) * 4;
    int mi = m0 + ar; if (mi > M - 1) mi = M - 1;       // clamp; masked at store
    const float* aptr = x + (size_t)g_tok[e * T_TOK + mi] * EMB + ac;

    // B (W1[e], [E][H] row-major): 32 threads per k-row, float4 each
    int bk = tid >> 5;
    int bn = (tid & 31) * 4;
    const float* bptr = W1 + (size_t)e * EMB * HID + (size_t)bk * HID + n0 + bn;

    float acc[8][8];
#pragma unroll
    for (int i = 0; i < 8; i++)
#pragma unroll
        for (int j = 0; j < 8; j++) acc[i][j] = 0.f;

    for (int k0 = 0; k0 < EMB; k0 += BK) {
        float4 av = *(const float4*)(aptr + k0);
        float4 bv = *(const float4*)(bptr + (size_t)k0 * HID);
        __syncthreads();
        As[ac + 0][ar] = av.x; As[ac + 1][ar] = av.y;
        As[ac + 2][ar] = av.z; As[ac + 3][ar] = av.w;
        *(float4*)&Bs[bk][bn] = bv;
        __syncthreads();
#pragma unroll
        for (int kk = 0; kk < BK; kk++) {
            float4 a0 = *(const float4*)&As[kk][ty * 8];
            float4 a1 = *(const float4*)&As[kk][ty * 8 + 4];
            float4 b0 = *(const float4*)&Bs[kk][tx * 8];
            float4 b1f = *(const float4*)&Bs[kk][tx * 8 + 4];
            float a[8] = {a0.x, a0.y, a0.z, a0.w, a1.x, a1.y, a1.z, a1.w};
            float b[8] = {b0.x, b0.y, b0.z, b0.w, b1f.x, b1f.y, b1f.z, b1f.w};
#pragma unroll
            for (int i = 0; i < 8; i++)
#pragma unroll
                for (int j = 0; j < 8; j++) acc[i][j] += a[i] * b[j];
        }
    }

    const int base = g_off[e];
    float bb[8];
#pragma unroll
    for (int j = 0; j < 8; j++) bb[j] = b1[(size_t)e * HID + n0 + tx * 8 + j];
#pragma unroll
    for (int i = 0; i < 8; i++) {
        int m = m0 + ty * 8 + i;
        if (m < M) {
            float* dst = g_h + (size_t)(base + m) * HID + n0 + tx * 8;
            float v[8];
#pragma unroll
            for (int j = 0; j < 8; j++) v[j] = gelu_exact(acc[i][j] + bb[j]);
            *(float4*)dst       = make_float4(v[0], v[1], v[2], v[3]);
            *(float4*)(dst + 4) = make_float4(v[4], v[5], v[6], v[7]);
        }
    }
}

// ---------------- kernel 5: grouped GEMM2  out += 0.5*(h @ W2[e] + b2) -----
// grid: (T_TOK/BM, EMB/BN, NE); block 256.
__global__ __launch_bounds__(256, 2) void gemm2_kernel(
        const float* __restrict__ W2, const float* __restrict__ b2,
        float* __restrict__ out) {
    const int e  = blockIdx.z;
    const int M  = g_cnt[e];
    const int m0 = blockIdx.x * BM;
    if (m0 >= M) return;
    const int n0 = blockIdx.y * BN;
    const int base = g_off[e];

    __shared__ float As[BK][BM];
    __shared__ float Bs[BK][BN];

    const int tid = threadIdx.x;
    const int tx = tid & 15, ty = tid >> 4;

    int ar = tid >> 1;
    int ac = (tid & 1) * 4;
    int mi = m0 + ar; if (mi > M - 1) mi = M - 1;
    const float* aptr = g_h + (size_t)(base + mi) * HID + ac;

    int bk = tid >> 5;
    int bn = (tid & 31) * 4;
    const float* bptr = W2 + (size_t)e * HID * EMB + (size_t)bk * EMB + n0 + bn;

    float acc[8][8];
#pragma unroll
    for (int i = 0; i < 8; i++)
#pragma unroll
        for (int j = 0; j < 8; j++) acc[i][j] = 0.f;

    for (int k0 = 0; k0 < HID; k0 += BK) {
        float4 av = *(const float4*)(aptr + k0);
        float4 bv = *(const float4*)(bptr + (size_t)k0 * EMB);
        __syncthreads();
        As[ac + 0][ar] = av.x; As[ac + 1][ar] = av.y;
        As[ac + 2][ar] = av.z; As[ac + 3][ar] = av.w;
        *(float4*)&Bs[bk][bn] = bv;
        __syncthreads();
#pragma unroll
        for (int kk = 0; kk < BK; kk++) {
            float4 a0 = *(const float4*)&As[kk][ty * 8];
            float4 a1 = *(const float4*)&As[kk][ty * 8 + 4];
            float4 b0 = *(const float4*)&Bs[kk][tx * 8];
            float4 b1f = *(const float4*)&Bs[kk][tx * 8 + 4];
            float a[8] = {a0.x, a0.y, a0.z, a0.w, a1.x, a1.y, a1.z, a1.w};
            float b[8] = {b0.x, b0.y, b0.z, b0.w, b1f.x, b1f.y, b1f.z, b1f.w};
#pragma unroll
            for (int i = 0; i < 8; i++)
#pragma unroll
                for (int j = 0; j < 8; j++) acc[i][j] += a[i] * b[j];
        }
    }

    float bb[8];
#pragma unroll
    for (int j = 0; j < 8; j++) bb[j] = b2[(size_t)e * EMB + n0 + tx * 8 + j];
#pragma unroll
    for (int i = 0; i < 8; i++) {
        int m = m0 + ty * 8 + i;
        if (m < M) {
            int tok = g_tok[e * T_TOK + m];
            float* dst = out + (size_t)tok * EMB + n0 + tx * 8;
            // exactly 2 contributions per output element -> commutative -> deterministic
#pragma unroll
            for (int j = 0; j < 8; j++)
                atomicAdd(dst + j, 0.5f * (acc[i][j] + bb[j]));
        }
    }
}

// ---------------- launch ----------------------------------------------------
extern "C" void kernel_launch(void* const* d_in, const int* in_sizes, int n_in,
                              void* d_out, int out_size) {
    const float* x  = (const float*)d_in[0];
    const float* Wr = (const float*)d_in[1];
    const float* br = (const float*)d_in[2];
    const float* W1 = (const float*)d_in[3];
    const float* b1 = (const float*)d_in[4];
    const float* W2 = (const float*)d_in[5];
    const float* b2 = (const float*)d_in[6];
    // d_in[7] is k (fixed at 2 for this dataset)
    float* out = (float*)d_out;

    int n4 = out_size / 4;  // out is fp32, out_size % 4 == 0 (T*E)
    zero_kernel<<<(n4 + 255) / 256, 256>>>((float4*)out, n4);
    router_kernel<<<T_TOK / 8, 256>>>(x, Wr, br);
    offs_kernel<<<1, 32>>>();
    gemm1_kernel<<<dim3(T_TOK / BM, HID / BN, NE), 256>>>(x, W1, b1);
    gemm2_kernel<<<dim3(T_TOK / BM, EMB / BN, NE), 256>>>(W2, b2, out);
}